// round 1
// baseline (speedup 1.0000x reference)
#include <cuda_runtime.h>

#define RES 256
#define NA  180
#define NB  4

__global__ __launch_bounds__(256) void radon_kernel(
    const float* __restrict__ imgs,
    const float* __restrict__ angles,
    const float* __restrict__ rays,
    float* __restrict__ out)
{
    const int ray = threadIdx.x;      // 0..255
    const int a   = blockIdx.x;       // angle
    const int b   = blockIdx.y;       // batch

    // Ray endpoints (rays stored row-major [256,4]: sx, sy, ex, ey)
    const float4 r4 = __ldg(reinterpret_cast<const float4*>(rays) + ray);
    const float sx = r4.x, sy = r4.y, ex = r4.z, ey = r4.w;

    const float ang = __ldg(angles + a);
    float s, c;
    sincosf(ang, &s, &c);

    // Rotate endpoints
    const float rsx = sx * c - sy * s;
    const float rsy = sx * s + sy * c;
    const float rex = ex * c - ey * s;
    const float rey = ex * s + ey * c;
    const float dx = rex - rsx;
    const float dy = rey - rsy;

    const float* __restrict__ img = imgs + (size_t)b * RES * RES;

    const float off = 127.5f;            // s - 0.5 with s = 128
    const float inv_n = 1.0f / RES;

    float acc = 0.0f;

    #pragma unroll 4
    for (int it = 0; it < RES; ++it) {
        const float t  = ((float)it + 0.5f) * inv_n;
        const float fx = rsx + dx * t + off;
        const float fy = rsy + dy * t + off;

        const float x0f = floorf(fx);
        const float y0f = floorf(fy);
        const int x0 = (int)x0f;
        const int y0 = (int)y0f;
        const float wx = fx - x0f;
        const float wy = fy - y0f;

        const int x1 = x0 + 1;
        const int y1 = y0 + 1;

        const bool vx0 = ((unsigned)x0 < RES);
        const bool vx1 = ((unsigned)x1 < RES);
        const bool vy0 = ((unsigned)y0 < RES);
        const bool vy1 = ((unsigned)y1 < RES);

        // clamped indices (match reference: clip then mask)
        const int xc0 = min(max(x0, 0), RES - 1);
        const int xc1 = min(max(x1, 0), RES - 1);
        const int yc0 = min(max(y0, 0), RES - 1);
        const int yc1 = min(max(y1, 0), RES - 1);

        const int row0 = yc0 * RES;
        const int row1 = yc1 * RES;

        float v00 = __ldg(img + row0 + xc0);
        float v01 = __ldg(img + row0 + xc1);
        float v10 = __ldg(img + row1 + xc0);
        float v11 = __ldg(img + row1 + xc1);

        v00 = (vx0 && vy0) ? v00 : 0.0f;
        v01 = (vx1 && vy0) ? v01 : 0.0f;
        v10 = (vx0 && vy1) ? v10 : 0.0f;
        v11 = (vx1 && vy1) ? v11 : 0.0f;

        const float top = (1.0f - wx) * v00 + wx * v01;
        const float bot = (1.0f - wx) * v10 + wx * v11;
        acc += (1.0f - wy) * top + wy * bot;
    }

    const float step = (ey - sy) * inv_n;   // L / n_steps
    out[((size_t)b * NA + a) * RES + ray] = acc * step;
}

extern "C" void kernel_launch(void* const* d_in, const int* in_sizes, int n_in,
                              void* d_out, int out_size)
{
    const float* imgs   = (const float*)d_in[0];   // [4,256,256]
    const float* angles = (const float*)d_in[1];   // [180]
    const float* rays   = (const float*)d_in[2];   // [256,4]
    float* out          = (float*)d_out;           // [4,180,256]

    dim3 grid(NA, NB);
    dim3 block(RES);
    radon_kernel<<<grid, block>>>(imgs, angles, rays, out);
}

// round 2
// speedup vs baseline: 1.8848x; 1.8848x over previous
#include <cuda_runtime.h>

#define RES 256
#define NA  180
#define NB  4
#define PW  257          // padded float2 cols: xp in [0,256]
#define PH  258          // padded rows: yp in [0,257]
#define BSZ (PH*PW)      // per-batch float2 count

// Padded, pair-duplicated image: P[b][yp][xp] = (pad[yp][xp-? ]...)
//   P[b][yp][xp].x = img[b][yp-1][xp-1]  (0 if OOB)
//   P[b][yp][xp].y = img[b][yp-1][xp]    (0 if OOB)
// => bilinear corners for (x0,y0): one float2 at idx=(y0+1)*PW+(x0+1) gives v00,v01,
//    one float2 at idx+PW gives v10,v11. Zero border implements boundary masking.
__device__ float2 g_P[NB * PH * PW];

__global__ __launch_bounds__(256) void prep_kernel(const float* __restrict__ imgs)
{
    int idx = blockIdx.x * blockDim.x + threadIdx.x;
    const int total = NB * PH * PW;
    if (idx >= total) return;
    int xp = idx % PW;
    int t  = idx / PW;
    int yp = t % PH;
    int b  = t / PH;
    int y  = yp - 1;
    int xa = xp - 1;
    float v0 = 0.0f, v1 = 0.0f;
    if ((unsigned)y < RES) {
        const float* row = imgs + ((size_t)b * RES + y) * RES;
        if ((unsigned)xa < RES) v0 = row[xa];
        if ((unsigned)xp < RES) v1 = row[xp];
    }
    g_P[idx] = make_float2(v0, v1);
}

__global__ __launch_bounds__(256) void radon_kernel(
    const float* __restrict__ angles,
    const float* __restrict__ rays,
    float* __restrict__ out)
{
    const int tid  = threadIdx.x;
    const int lane = tid & 31;
    const int warp = tid >> 5;        // 0..7
    const int r8   = lane & 7;        // ray within warp tile
    const int t4   = lane >> 3;       // t-phase 0..3
    const int a    = blockIdx.x;      // angle
    const int rg   = blockIdx.y;      // ray group 0..3
    const int ray  = rg * 64 + warp * 8 + r8;

    const float4 r4 = __ldg(reinterpret_cast<const float4*>(rays) + ray);
    float s, c;
    sincosf(__ldg(angles + a), &s, &c);

    const float rsx = r4.x * c - r4.y * s;
    const float rsy = r4.x * s + r4.y * c;
    const float dx  = (r4.z * c - r4.w * s) - rsx;
    const float dy  = (r4.z * s + r4.w * c) - rsy;

    const float inv_n = 1.0f / RES;
    // +128.5 folds the image-center offset (127.5) and the +1 padding shift.
    float gx = rsx + 128.5f + dx * inv_n * ((float)t4 + 0.5f);
    float gy = rsy + 128.5f + dy * inv_n * ((float)t4 + 0.5f);
    const float sx4 = dx * inv_n * 4.0f;
    const float sy4 = dy * inv_n * 4.0f;

    const float2* __restrict__ P = g_P;

    float acc0 = 0.f, acc1 = 0.f, acc2 = 0.f, acc3 = 0.f;

    #pragma unroll 2
    for (int i = 0; i < 64; ++i) {
        const int x0 = __float2int_rd(gx);
        const int y0 = __float2int_rd(gy);
        const float wx = gx - (float)x0;
        const float wy = gy - (float)y0;
        const int idx = y0 * PW + x0;

        const float2 t0 = __ldg(P + idx);
        const float2 b0 = __ldg(P + idx + PW);
        const float2 t1 = __ldg(P + BSZ + idx);
        const float2 b1 = __ldg(P + BSZ + idx + PW);
        const float2 t2 = __ldg(P + 2 * BSZ + idx);
        const float2 b2 = __ldg(P + 2 * BSZ + idx + PW);
        const float2 t3 = __ldg(P + 3 * BSZ + idx);
        const float2 b3 = __ldg(P + 3 * BSZ + idx + PW);

        {
            const float top = t0.x + wx * (t0.y - t0.x);
            const float bot = b0.x + wx * (b0.y - b0.x);
            acc0 += top + wy * (bot - top);
        }
        {
            const float top = t1.x + wx * (t1.y - t1.x);
            const float bot = b1.x + wx * (b1.y - b1.x);
            acc1 += top + wy * (bot - top);
        }
        {
            const float top = t2.x + wx * (t2.y - t2.x);
            const float bot = b2.x + wx * (b2.y - b2.x);
            acc2 += top + wy * (bot - top);
        }
        {
            const float top = t3.x + wx * (t3.y - t3.x);
            const float bot = b3.x + wx * (b3.y - b3.x);
            acc3 += top + wy * (bot - top);
        }

        gx += sx4;
        gy += sy4;
    }

    // Reduce the 4 t-phases of each ray (lanes l, l+8, l+16, l+24).
    acc0 += __shfl_xor_sync(0xFFFFFFFFu, acc0, 8);
    acc0 += __shfl_xor_sync(0xFFFFFFFFu, acc0, 16);
    acc1 += __shfl_xor_sync(0xFFFFFFFFu, acc1, 8);
    acc1 += __shfl_xor_sync(0xFFFFFFFFu, acc1, 16);
    acc2 += __shfl_xor_sync(0xFFFFFFFFu, acc2, 8);
    acc2 += __shfl_xor_sync(0xFFFFFFFFu, acc2, 16);
    acc3 += __shfl_xor_sync(0xFFFFFFFFu, acc3, 8);
    acc3 += __shfl_xor_sync(0xFFFFFFFFu, acc3, 16);

    if (t4 == 0) {
        const float step = (r4.w - r4.y) * inv_n;   // L / n_steps
        const int base = a * RES + ray;
        out[0 * NA * RES + base] = acc0 * step;
        out[1 * NA * RES + base] = acc1 * step;
        out[2 * NA * RES + base] = acc2 * step;
        out[3 * NA * RES + base] = acc3 * step;
    }
}

extern "C" void kernel_launch(void* const* d_in, const int* in_sizes, int n_in,
                              void* d_out, int out_size)
{
    const float* imgs   = (const float*)d_in[0];   // [4,256,256]
    const float* angles = (const float*)d_in[1];   // [180]
    const float* rays   = (const float*)d_in[2];   // [256,4]
    float* out          = (float*)d_out;           // [4,180,256]

    const int total = NB * PH * PW;
    prep_kernel<<<(total + 255) / 256, 256>>>(imgs);

    dim3 grid(NA, 4);
    radon_kernel<<<grid, 256>>>(angles, rays, out);
}

// round 3
// speedup vs baseline: 3.8611x; 2.0485x over previous
#include <cuda_runtime.h>
#include <cuda_fp16.h>

#define RES 256
#define NA  180
#define NB  4
#define PW  257            // x0p in [0,256]
#define PH  257            // y0p in [0,256]
#define NPIX (PH*PW)

// Corner-packed fp16 images. For padded pixel (yp,xp) (maps to sample floor
// (x0,y0) = (xp-1, yp-1)):
//   g_A01[yp*PW+xp] = { h2(b0.v00,b0.v01), h2(b0.v10,b0.v11),
//                       h2(b1.v00,b1.v01), h2(b1.v10,b1.v11) }
//   g_A23: same for batches 2,3.
// vXY = img[y0+X][x0+Y], OOB -> 0 (zero border = reference's validity mask).
__device__ uint4 g_A01[NPIX];
__device__ uint4 g_A23[NPIX];

__device__ __forceinline__ unsigned pack2(float a, float b) {
    __half2 h = __floats2half2_rn(a, b);
    return *reinterpret_cast<unsigned*>(&h);
}
__device__ __forceinline__ float2 unpack2(unsigned u) {
    __half2 h = *reinterpret_cast<__half2*>(&u);
    return __half22float2(h);
}

__global__ __launch_bounds__(256) void prep_kernel(const float* __restrict__ imgs)
{
    int idx = blockIdx.x * blockDim.x + threadIdx.x;
    if (idx >= NPIX) return;
    const int xp = idx % PW;
    const int yp = idx / PW;
    const int yt = yp - 1, yb = yp;
    const int xl = xp - 1, xr = xp;

    float v[NB][4];
    #pragma unroll
    for (int b = 0; b < NB; ++b) {
        const float* im = imgs + (size_t)b * RES * RES;
        const bool vt = ((unsigned)yt < RES), vb = ((unsigned)yb < RES);
        const bool vl = ((unsigned)xl < RES), vr = ((unsigned)xr < RES);
        v[b][0] = (vt && vl) ? im[yt * RES + xl] : 0.0f;   // v00
        v[b][1] = (vt && vr) ? im[yt * RES + xr] : 0.0f;   // v01
        v[b][2] = (vb && vl) ? im[yb * RES + xl] : 0.0f;   // v10
        v[b][3] = (vb && vr) ? im[yb * RES + xr] : 0.0f;   // v11
    }
    uint4 qa, qb;
    qa.x = pack2(v[0][0], v[0][1]);  qa.y = pack2(v[0][2], v[0][3]);
    qa.z = pack2(v[1][0], v[1][1]);  qa.w = pack2(v[1][2], v[1][3]);
    qb.x = pack2(v[2][0], v[2][1]);  qb.y = pack2(v[2][2], v[2][3]);
    qb.z = pack2(v[3][0], v[3][1]);  qb.w = pack2(v[3][2], v[3][3]);
    g_A01[idx] = qa;
    g_A23[idx] = qb;
}

__device__ __forceinline__ void bilerp_acc(unsigned top, unsigned bot,
                                           float wx, float wy, float& acc)
{
    const float2 T = unpack2(top);
    const float2 B = unpack2(bot);
    const float ft = fmaf(wx, T.y - T.x, T.x);
    const float fb = fmaf(wx, B.y - B.x, B.x);
    acc += fmaf(wy, fb - ft, ft);
}

__global__ __launch_bounds__(256) void radon_kernel(
    const float* __restrict__ angles,
    const float* __restrict__ rays,
    float* __restrict__ out)
{
    const int tid  = threadIdx.x;
    const int lane = tid & 31;
    const int warp = tid >> 5;        // 0..7
    const int r8   = lane & 7;        // ray within warp tile
    const int t4   = lane >> 3;       // t-phase 0..3
    const int a    = blockIdx.x;      // angle
    const int rg   = blockIdx.y;      // ray group 0..3
    const int ray  = rg * 64 + warp * 8 + r8;

    const float4 r4 = __ldg(reinterpret_cast<const float4*>(rays) + ray);
    float s, c;
    sincosf(__ldg(angles + a), &s, &c);

    const float rsx = r4.x * c - r4.y * s;
    const float rsy = r4.x * s + r4.y * c;
    const float dx  = (r4.z * c - r4.w * s) - rsx;
    const float dy  = (r4.z * s + r4.w * c) - rsy;

    const float inv_n = 1.0f / RES;
    // +128.5 folds image-center offset (127.5) and the +1 padding shift.
    float gx = rsx + 128.5f + dx * inv_n * ((float)t4 + 0.5f);
    float gy = rsy + 128.5f + dy * inv_n * ((float)t4 + 0.5f);
    const float sx4 = dx * inv_n * 4.0f;
    const float sy4 = dy * inv_n * 4.0f;

    float acc0 = 0.f, acc1 = 0.f, acc2 = 0.f, acc3 = 0.f;

    #pragma unroll 4
    for (int i = 0; i < 64; ++i) {
        const int x0 = __float2int_rd(gx);
        const int y0 = __float2int_rd(gy);
        const float wx = gx - (float)x0;
        const float wy = gy - (float)y0;
        const int idx = y0 * PW + x0;

        const uint4 qa = __ldg(g_A01 + idx);
        const uint4 qb = __ldg(g_A23 + idx);

        bilerp_acc(qa.x, qa.y, wx, wy, acc0);
        bilerp_acc(qa.z, qa.w, wx, wy, acc1);
        bilerp_acc(qb.x, qb.y, wx, wy, acc2);
        bilerp_acc(qb.z, qb.w, wx, wy, acc3);

        gx += sx4;
        gy += sy4;
    }

    // Reduce the 4 t-phases of each ray (lanes l, l+8, l+16, l+24).
    acc0 += __shfl_xor_sync(0xFFFFFFFFu, acc0, 8);
    acc0 += __shfl_xor_sync(0xFFFFFFFFu, acc0, 16);
    acc1 += __shfl_xor_sync(0xFFFFFFFFu, acc1, 8);
    acc1 += __shfl_xor_sync(0xFFFFFFFFu, acc1, 16);
    acc2 += __shfl_xor_sync(0xFFFFFFFFu, acc2, 8);
    acc2 += __shfl_xor_sync(0xFFFFFFFFu, acc2, 16);
    acc3 += __shfl_xor_sync(0xFFFFFFFFu, acc3, 8);
    acc3 += __shfl_xor_sync(0xFFFFFFFFu, acc3, 16);

    if (t4 == 0) {
        const float step = (r4.w - r4.y) * inv_n;   // L / n_steps
        const int base = a * RES + ray;
        out[0 * NA * RES + base] = acc0 * step;
        out[1 * NA * RES + base] = acc1 * step;
        out[2 * NA * RES + base] = acc2 * step;
        out[3 * NA * RES + base] = acc3 * step;
    }
}

extern "C" void kernel_launch(void* const* d_in, const int* in_sizes, int n_in,
                              void* d_out, int out_size)
{
    const float* imgs   = (const float*)d_in[0];   // [4,256,256]
    const float* angles = (const float*)d_in[1];   // [180]
    const float* rays   = (const float*)d_in[2];   // [256,4]
    float* out          = (float*)d_out;           // [4,180,256]

    prep_kernel<<<(NPIX + 255) / 256, 256>>>(imgs);

    dim3 grid(NA, 4);
    radon_kernel<<<grid, 256>>>(angles, rays, out);
}

// round 5
// speedup vs baseline: 3.9583x; 1.0252x over previous
#include <cuda_runtime.h>
#include <cuda_fp16.h>

#define RES 256
#define NA  180
#define NB  4
#define PW  257            // x0p in [0,256]
#define PH  257            // y0p in [0,256]
#define NPIX (PH*PW)
#define NOUT (NB*NA*RES)

// Corner-packed fp16 images. For padded pixel (yp,xp) (maps to sample floor
// (x0,y0) = (xp-1, yp-1)):
//   g_A01[yp*PW+xp] = { h2(b0.v00,b0.v01), h2(b0.v10,b0.v11),
//                       h2(b1.v00,b1.v01), h2(b1.v10,b1.v11) }
//   g_A23: same for batches 2,3.
// vXY = img[y0+X][x0+Y], OOB -> 0 (zero border = reference's validity mask).
__device__ uint4 g_A01[NPIX];
__device__ uint4 g_A23[NPIX];

__device__ __forceinline__ unsigned pack2(float a, float b) {
    __half2 h = __floats2half2_rn(a, b);
    return *reinterpret_cast<unsigned*>(&h);
}
__device__ __forceinline__ float2 unpack2(unsigned u) {
    __half2 h = *reinterpret_cast<__half2*>(&u);
    return __half22float2(h);
}

// Prep: build corner-packed arrays AND zero the output (radon adds atomically).
__global__ __launch_bounds__(256) void prep_kernel(const float* __restrict__ imgs,
                                                   float* __restrict__ out)
{
    int idx = blockIdx.x * blockDim.x + threadIdx.x;
    if (idx < NOUT) out[idx] = 0.0f;
    if (idx >= NPIX) return;
    const int xp = idx % PW;
    const int yp = idx / PW;
    const int yt = yp - 1, yb = yp;
    const int xl = xp - 1, xr = xp;

    float v[NB][4];
    #pragma unroll
    for (int b = 0; b < NB; ++b) {
        const float* im = imgs + (size_t)b * RES * RES;
        const bool vt = ((unsigned)yt < RES), vb = ((unsigned)yb < RES);
        const bool vl = ((unsigned)xl < RES), vr = ((unsigned)xr < RES);
        v[b][0] = (vt && vl) ? im[yt * RES + xl] : 0.0f;   // v00
        v[b][1] = (vt && vr) ? im[yt * RES + xr] : 0.0f;   // v01
        v[b][2] = (vb && vl) ? im[yb * RES + xl] : 0.0f;   // v10
        v[b][3] = (vb && vr) ? im[yb * RES + xr] : 0.0f;   // v11
    }
    uint4 qa, qb;
    qa.x = pack2(v[0][0], v[0][1]);  qa.y = pack2(v[0][2], v[0][3]);
    qa.z = pack2(v[1][0], v[1][1]);  qa.w = pack2(v[1][2], v[1][3]);
    qb.x = pack2(v[2][0], v[2][1]);  qb.y = pack2(v[2][2], v[2][3]);
    qb.z = pack2(v[3][0], v[3][1]);  qb.w = pack2(v[3][2], v[3][3]);
    g_A01[idx] = qa;
    g_A23[idx] = qb;
}

__device__ __forceinline__ void bilerp_acc(unsigned top, unsigned bot,
                                           float wx, float wy, float& acc)
{
    const float2 T = unpack2(top);
    const float2 B = unpack2(bot);
    const float ft = fmaf(wx, T.y - T.x, T.x);
    const float fb = fmaf(wx, B.y - B.x, B.x);
    acc += fmaf(wy, fb - ft, ft);
}

// Block = 128 threads (4 warps). Warp tile: 8 rays x 4 t-phases.
// Grid: (angle, ray_group 0..7, t_half 0..1).
// Each block: 32 rays x 128 t-steps (t4 + 4*i + th*128, i in [0,32)).
__global__ __launch_bounds__(128) void radon_kernel(
    const float* __restrict__ angles,
    const float* __restrict__ rays,
    float* __restrict__ out)
{
    const int tid  = threadIdx.x;
    const int lane = tid & 31;
    const int warp = tid >> 5;        // 0..3
    const int r8   = lane & 7;        // ray within warp tile
    const int t4   = lane >> 3;       // t-phase 0..3
    const int a    = blockIdx.x;      // angle
    const int rg   = blockIdx.y;      // ray group 0..7
    const int th   = blockIdx.z;      // t half 0..1
    const int ray  = rg * 32 + warp * 8 + r8;

    const float4 r4 = __ldg(reinterpret_cast<const float4*>(rays) + ray);
    float s, c;
    sincosf(__ldg(angles + a), &s, &c);

    const float rsx = r4.x * c - r4.y * s;
    const float rsy = r4.x * s + r4.y * c;
    const float dx  = (r4.z * c - r4.w * s) - rsx;
    const float dy  = (r4.z * s + r4.w * c) - rsy;

    const float inv_n = 1.0f / RES;
    const float t0 = (float)(th * 128 + t4) + 0.5f;
    // +128.5 folds image-center offset (127.5) and the +1 padding shift.
    float gx = rsx + 128.5f + dx * inv_n * t0;
    float gy = rsy + 128.5f + dy * inv_n * t0;
    const float sx4 = dx * inv_n * 4.0f;
    const float sy4 = dy * inv_n * 4.0f;

    float acc0 = 0.f, acc1 = 0.f, acc2 = 0.f, acc3 = 0.f;

    #pragma unroll 8
    for (int i = 0; i < 32; ++i) {
        const int x0 = __float2int_rd(gx);
        const int y0 = __float2int_rd(gy);
        const float wx = gx - (float)x0;
        const float wy = gy - (float)y0;
        const int idx = y0 * PW + x0;

        const uint4 qa = __ldg(g_A01 + idx);
        const uint4 qb = __ldg(g_A23 + idx);

        bilerp_acc(qa.x, qa.y, wx, wy, acc0);
        bilerp_acc(qa.z, qa.w, wx, wy, acc1);
        bilerp_acc(qb.x, qb.y, wx, wy, acc2);
        bilerp_acc(qb.z, qb.w, wx, wy, acc3);

        gx += sx4;
        gy += sy4;
    }

    // Reduce the 4 t-phases of each ray (lanes l, l+8, l+16, l+24).
    acc0 += __shfl_xor_sync(0xFFFFFFFFu, acc0, 8);
    acc0 += __shfl_xor_sync(0xFFFFFFFFu, acc0, 16);
    acc1 += __shfl_xor_sync(0xFFFFFFFFu, acc1, 8);
    acc1 += __shfl_xor_sync(0xFFFFFFFFu, acc1, 16);
    acc2 += __shfl_xor_sync(0xFFFFFFFFu, acc2, 8);
    acc2 += __shfl_xor_sync(0xFFFFFFFFu, acc2, 16);
    acc3 += __shfl_xor_sync(0xFFFFFFFFu, acc3, 8);
    acc3 += __shfl_xor_sync(0xFFFFFFFFu, acc3, 16);

    if (t4 == 0) {
        const float step = (r4.w - r4.y) * inv_n;   // L / n_steps
        const int base = a * RES + ray;
        atomicAdd(out + 0 * NA * RES + base, acc0 * step);
        atomicAdd(out + 1 * NA * RES + base, acc1 * step);
        atomicAdd(out + 2 * NA * RES + base, acc2 * step);
        atomicAdd(out + 3 * NA * RES + base, acc3 * step);
    }
}

extern "C" void kernel_launch(void* const* d_in, const int* in_sizes, int n_in,
                              void* d_out, int out_size)
{
    const float* imgs   = (const float*)d_in[0];   // [4,256,256]
    const float* angles = (const float*)d_in[1];   // [180]
    const float* rays   = (const float*)d_in[2];   // [256,4]
    float* out          = (float*)d_out;           // [4,180,256]

    const int prep_threads = (NOUT > NPIX ? NOUT : NPIX);
    prep_kernel<<<(prep_threads + 255) / 256, 256>>>(imgs, out);

    dim3 grid(NA, 8, 2);
    radon_kernel<<<grid, 128>>>(angles, rays, out);
}

// round 6
// speedup vs baseline: 5.8471x; 1.4772x over previous
#include <cuda_runtime.h>
#include <cuda_fp16.h>

#define RES 256
#define NA  180
#define NB  4
#define PW  257            // x0p in [0,256]
#define PH  257            // y0p in [0,256]
#define NPIX (PH*PW)
#define NOUT (NB*NA*RES)

// Corner-packed fp16 images, all 4 batches interleaved: 32 bytes per padded
// pixel. For padded pixel (yp,xp) (sample floor (x0,y0) = (xp-1, yp-1)):
//   g_P[idx].a = { h2(b0.v00,b0.v01), h2(b0.v10,b0.v11),
//                  h2(b1.v00,b1.v01), h2(b1.v10,b1.v11) }
//   g_P[idx].b = same for batches 2,3.
// vXY = img[y0+X][x0+Y], OOB -> 0 (zero border = reference's validity mask).
struct __align__(32) Px { uint4 a, b; };
__device__ Px g_P[NPIX];

__device__ __forceinline__ unsigned pack2(float a, float b) {
    __half2 h = __floats2half2_rn(a, b);
    return *reinterpret_cast<unsigned*>(&h);
}
__device__ __forceinline__ float2 unpack2(unsigned u) {
    __half2 h = *reinterpret_cast<__half2*>(&u);
    return __half22float2(h);
}

// 256-bit global load (sm_100+).
__device__ __forceinline__ void ldg256(const Px* p, uint4& a, uint4& b) {
    asm volatile("ld.global.nc.v8.u32 {%0,%1,%2,%3,%4,%5,%6,%7}, [%8];"
                 : "=r"(a.x), "=r"(a.y), "=r"(a.z), "=r"(a.w),
                   "=r"(b.x), "=r"(b.y), "=r"(b.z), "=r"(b.w)
                 : "l"(p));
}

// Prep: build corner-packed array AND zero the output (radon adds atomically).
__global__ __launch_bounds__(256) void prep_kernel(const float* __restrict__ imgs,
                                                   float* __restrict__ out)
{
    int idx = blockIdx.x * blockDim.x + threadIdx.x;
    if (idx < NOUT) out[idx] = 0.0f;
    if (idx >= NPIX) return;
    const int xp = idx % PW;
    const int yp = idx / PW;
    const int yt = yp - 1, yb = yp;
    const int xl = xp - 1, xr = xp;

    float v[NB][4];
    #pragma unroll
    for (int b = 0; b < NB; ++b) {
        const float* im = imgs + (size_t)b * RES * RES;
        const bool vt = ((unsigned)yt < RES), vb = ((unsigned)yb < RES);
        const bool vl = ((unsigned)xl < RES), vr = ((unsigned)xr < RES);
        v[b][0] = (vt && vl) ? im[yt * RES + xl] : 0.0f;   // v00
        v[b][1] = (vt && vr) ? im[yt * RES + xr] : 0.0f;   // v01
        v[b][2] = (vb && vl) ? im[yb * RES + xl] : 0.0f;   // v10
        v[b][3] = (vb && vr) ? im[yb * RES + xr] : 0.0f;   // v11
    }
    Px px;
    px.a.x = pack2(v[0][0], v[0][1]);  px.a.y = pack2(v[0][2], v[0][3]);
    px.a.z = pack2(v[1][0], v[1][1]);  px.a.w = pack2(v[1][2], v[1][3]);
    px.b.x = pack2(v[2][0], v[2][1]);  px.b.y = pack2(v[2][2], v[2][3]);
    px.b.z = pack2(v[3][0], v[3][1]);  px.b.w = pack2(v[3][2], v[3][3]);
    g_P[idx] = px;
}

__device__ __forceinline__ void bilerp_acc(unsigned top, unsigned bot,
                                           float wx, float wy, float& acc)
{
    const float2 T = unpack2(top);
    const float2 B = unpack2(bot);
    const float ft = fmaf(wx, T.y - T.x, T.x);
    const float fb = fmaf(wx, B.y - B.x, B.x);
    acc += fmaf(wy, fb - ft, ft);
}

// Block = 128 threads (4 warps). Warp tile: 8 rays x 4 t-phases.
// Grid: (angle, ray_group 0..7, t_half 0..1).
// Each block: 32 rays x 128 t-steps (t = th*128 + 4*i + t4, i in [0,32)).
__global__ __launch_bounds__(128) void radon_kernel(
    const float* __restrict__ angles,
    const float* __restrict__ rays,
    float* __restrict__ out)
{
    const int tid  = threadIdx.x;
    const int lane = tid & 31;
    const int warp = tid >> 5;        // 0..3
    const int r8   = lane & 7;        // ray within warp tile
    const int t4   = lane >> 3;       // t-phase 0..3
    const int a    = blockIdx.x;      // angle
    const int rg   = blockIdx.y;      // ray group 0..7
    const int th   = blockIdx.z;      // t half 0..1
    const int ray  = rg * 32 + warp * 8 + r8;

    const float4 r4 = __ldg(reinterpret_cast<const float4*>(rays) + ray);
    float s, c;
    sincosf(__ldg(angles + a), &s, &c);

    const float rsx = r4.x * c - r4.y * s;
    const float rsy = r4.x * s + r4.y * c;
    const float dx  = (r4.z * c - r4.w * s) - rsx;
    const float dy  = (r4.z * s + r4.w * c) - rsy;

    const float inv_n = 1.0f / RES;
    const float t0 = (float)(th * 128 + t4) + 0.5f;
    // +128.5 folds image-center offset (127.5) and the +1 padding shift.
    float gx = rsx + 128.5f + dx * inv_n * t0;
    float gy = rsy + 128.5f + dy * inv_n * t0;
    const float sx4 = dx * inv_n * 4.0f;
    const float sy4 = dy * inv_n * 4.0f;

    float acc0 = 0.f, acc1 = 0.f, acc2 = 0.f, acc3 = 0.f;

    #pragma unroll 8
    for (int i = 0; i < 32; ++i) {
        const int x0 = __float2int_rd(gx);
        const int y0 = __float2int_rd(gy);
        const float wx = gx - (float)x0;
        const float wy = gy - (float)y0;
        const int idx = y0 * PW + x0;

        uint4 qa, qb;
        ldg256(g_P + idx, qa, qb);

        bilerp_acc(qa.x, qa.y, wx, wy, acc0);
        bilerp_acc(qa.z, qa.w, wx, wy, acc1);
        bilerp_acc(qb.x, qb.y, wx, wy, acc2);
        bilerp_acc(qb.z, qb.w, wx, wy, acc3);

        gx += sx4;
        gy += sy4;
    }

    // Reduce the 4 t-phases of each ray (lanes l, l+8, l+16, l+24).
    acc0 += __shfl_xor_sync(0xFFFFFFFFu, acc0, 8);
    acc0 += __shfl_xor_sync(0xFFFFFFFFu, acc0, 16);
    acc1 += __shfl_xor_sync(0xFFFFFFFFu, acc1, 8);
    acc1 += __shfl_xor_sync(0xFFFFFFFFu, acc1, 16);
    acc2 += __shfl_xor_sync(0xFFFFFFFFu, acc2, 8);
    acc2 += __shfl_xor_sync(0xFFFFFFFFu, acc2, 16);
    acc3 += __shfl_xor_sync(0xFFFFFFFFu, acc3, 8);
    acc3 += __shfl_xor_sync(0xFFFFFFFFu, acc3, 16);

    if (t4 == 0) {
        const float step = (r4.w - r4.y) * inv_n;   // L / n_steps
        const int base = a * RES + ray;
        atomicAdd(out + 0 * NA * RES + base, acc0 * step);
        atomicAdd(out + 1 * NA * RES + base, acc1 * step);
        atomicAdd(out + 2 * NA * RES + base, acc2 * step);
        atomicAdd(out + 3 * NA * RES + base, acc3 * step);
    }
}

extern "C" void kernel_launch(void* const* d_in, const int* in_sizes, int n_in,
                              void* d_out, int out_size)
{
    const float* imgs   = (const float*)d_in[0];   // [4,256,256]
    const float* angles = (const float*)d_in[1];   // [180]
    const float* rays   = (const float*)d_in[2];   // [256,4]
    float* out          = (float*)d_out;           // [4,180,256]

    const int prep_threads = (NOUT > NPIX ? NOUT : NPIX);
    prep_kernel<<<(prep_threads + 255) / 256, 256>>>(imgs, out);

    dim3 grid(NA, 8, 2);
    radon_kernel<<<grid, 128>>>(angles, rays, out);
}

// round 7
// speedup vs baseline: 5.9681x; 1.0207x over previous
#include <cuda_runtime.h>
#include <cuda_fp16.h>

#define RES 256
#define NA  180
#define NB  4
#define PW  257            // x0p in [0,256]
#define PH  257            // y0p in [0,256]
#define NPIX (PH*PW)
#define NOUT (NB*NA*RES)

// Corner-packed fp16 images, batches interleaved INSIDE each half2 so the
// bilerp runs as half2 SIMD over batch pairs. 32 bytes per padded pixel:
//   w0 = h2(b0.v00, b1.v00)   w4 = h2(b2.v00, b3.v00)
//   w1 = h2(b0.v01, b1.v01)   w5 = h2(b2.v01, b3.v01)
//   w2 = h2(b0.v10, b1.v10)   w6 = h2(b2.v10, b3.v10)
//   w3 = h2(b0.v11, b1.v11)   w7 = h2(b2.v11, b3.v11)
// vXY = img[y0+X][x0+Y], OOB -> 0 (zero border = reference's validity mask).
struct __align__(32) Px { uint4 a, b; };
__device__ Px g_P[NPIX];

__device__ __forceinline__ unsigned pack2(float a, float b) {
    __half2 h = __floats2half2_rn(a, b);
    return *reinterpret_cast<unsigned*>(&h);
}
__device__ __forceinline__ __half2 as_h2(unsigned u) {
    return *reinterpret_cast<__half2*>(&u);
}

// 256-bit global load (sm_100+).
__device__ __forceinline__ void ldg256(const Px* p, uint4& a, uint4& b) {
    asm volatile("ld.global.nc.v8.u32 {%0,%1,%2,%3,%4,%5,%6,%7}, [%8];"
                 : "=r"(a.x), "=r"(a.y), "=r"(a.z), "=r"(a.w),
                   "=r"(b.x), "=r"(b.y), "=r"(b.z), "=r"(b.w)
                 : "l"(p));
}

// Prep: build corner-packed array AND zero the output (radon adds atomically).
__global__ __launch_bounds__(256) void prep_kernel(const float* __restrict__ imgs,
                                                   float* __restrict__ out)
{
    int idx = blockIdx.x * blockDim.x + threadIdx.x;
    if (idx < NOUT) out[idx] = 0.0f;
    if (idx >= NPIX) return;
    const int xp = idx % PW;
    const int yp = idx / PW;
    const int yt = yp - 1, yb = yp;
    const int xl = xp - 1, xr = xp;

    float v[NB][4];
    #pragma unroll
    for (int b = 0; b < NB; ++b) {
        const float* im = imgs + (size_t)b * RES * RES;
        const bool vt = ((unsigned)yt < RES), vb = ((unsigned)yb < RES);
        const bool vl = ((unsigned)xl < RES), vr = ((unsigned)xr < RES);
        v[b][0] = (vt && vl) ? im[yt * RES + xl] : 0.0f;   // v00
        v[b][1] = (vt && vr) ? im[yt * RES + xr] : 0.0f;   // v01
        v[b][2] = (vb && vl) ? im[yb * RES + xl] : 0.0f;   // v10
        v[b][3] = (vb && vr) ? im[yb * RES + xr] : 0.0f;   // v11
    }
    Px px;
    px.a.x = pack2(v[0][0], v[1][0]);   // v00 of b0,b1
    px.a.y = pack2(v[0][1], v[1][1]);   // v01
    px.a.z = pack2(v[0][2], v[1][2]);   // v10
    px.a.w = pack2(v[0][3], v[1][3]);   // v11
    px.b.x = pack2(v[2][0], v[3][0]);
    px.b.y = pack2(v[2][1], v[3][1]);
    px.b.z = pack2(v[2][2], v[3][2]);
    px.b.w = pack2(v[2][3], v[3][3]);
    g_P[idx] = px;
}

// Bilerp for a batch pair, fully in half2 SIMD; returns float2 sample.
__device__ __forceinline__ float2 bilerp_h2(const uint4& q,
                                            __half2 wx2, __half2 wy2)
{
    const __half2 v00 = as_h2(q.x), v01 = as_h2(q.y);
    const __half2 v10 = as_h2(q.z), v11 = as_h2(q.w);
    const __half2 top = __hfma2(wx2, __hsub2(v01, v00), v00);
    const __half2 bot = __hfma2(wx2, __hsub2(v11, v10), v10);
    const __half2 smp = __hfma2(wy2, __hsub2(bot, top), top);
    return __half22float2(smp);
}

// Block = 128 threads (4 warps). Warp tile: 8 rays x 4 t-phases.
// Grid: (angle, ray_group 0..7, t_half 0..1).
// Each block: 32 rays x 128 t-steps (t = th*128 + 4*i + t4, i in [0,32)).
__global__ __launch_bounds__(128) void radon_kernel(
    const float* __restrict__ angles,
    const float* __restrict__ rays,
    float* __restrict__ out)
{
    const int tid  = threadIdx.x;
    const int lane = tid & 31;
    const int warp = tid >> 5;        // 0..3
    const int r8   = lane & 7;        // ray within warp tile
    const int t4   = lane >> 3;       // t-phase 0..3
    const int a    = blockIdx.x;      // angle
    const int rg   = blockIdx.y;      // ray group 0..7
    const int th   = blockIdx.z;      // t half 0..1
    const int ray  = rg * 32 + warp * 8 + r8;

    const float4 r4 = __ldg(reinterpret_cast<const float4*>(rays) + ray);
    float s, c;
    sincosf(__ldg(angles + a), &s, &c);

    const float rsx = r4.x * c - r4.y * s;
    const float rsy = r4.x * s + r4.y * c;
    const float dx  = (r4.z * c - r4.w * s) - rsx;
    const float dy  = (r4.z * s + r4.w * c) - rsy;

    const float inv_n = 1.0f / RES;
    const float t0 = (float)(th * 128 + t4) + 0.5f;
    // +128.5 folds image-center offset (127.5) and the +1 padding shift.
    float gx = rsx + 128.5f + dx * inv_n * t0;
    float gy = rsy + 128.5f + dy * inv_n * t0;
    const float sx4 = dx * inv_n * 4.0f;
    const float sy4 = dy * inv_n * 4.0f;

    float acc0 = 0.f, acc1 = 0.f, acc2 = 0.f, acc3 = 0.f;

    #pragma unroll 8
    for (int i = 0; i < 32; ++i) {
        const int x0 = __float2int_rd(gx);
        const int y0 = __float2int_rd(gy);
        const float wx = gx - (float)x0;
        const float wy = gy - (float)y0;
        const int idx = y0 * PW + x0;

        uint4 qa, qb;
        ldg256(g_P + idx, qa, qb);

        const __half2 wx2 = __floats2half2_rn(wx, wx);
        const __half2 wy2 = __floats2half2_rn(wy, wy);

        const float2 s01 = bilerp_h2(qa, wx2, wy2);
        const float2 s23 = bilerp_h2(qb, wx2, wy2);
        acc0 += s01.x;  acc1 += s01.y;
        acc2 += s23.x;  acc3 += s23.y;

        gx += sx4;
        gy += sy4;
    }

    // Reduce the 4 t-phases of each ray (lanes l, l+8, l+16, l+24).
    acc0 += __shfl_xor_sync(0xFFFFFFFFu, acc0, 8);
    acc0 += __shfl_xor_sync(0xFFFFFFFFu, acc0, 16);
    acc1 += __shfl_xor_sync(0xFFFFFFFFu, acc1, 8);
    acc1 += __shfl_xor_sync(0xFFFFFFFFu, acc1, 16);
    acc2 += __shfl_xor_sync(0xFFFFFFFFu, acc2, 8);
    acc2 += __shfl_xor_sync(0xFFFFFFFFu, acc2, 16);
    acc3 += __shfl_xor_sync(0xFFFFFFFFu, acc3, 8);
    acc3 += __shfl_xor_sync(0xFFFFFFFFu, acc3, 16);

    if (t4 == 0) {
        const float step = (r4.w - r4.y) * inv_n;   // L / n_steps
        const int base = a * RES + ray;
        atomicAdd(out + 0 * NA * RES + base, acc0 * step);
        atomicAdd(out + 1 * NA * RES + base, acc1 * step);
        atomicAdd(out + 2 * NA * RES + base, acc2 * step);
        atomicAdd(out + 3 * NA * RES + base, acc3 * step);
    }
}

extern "C" void kernel_launch(void* const* d_in, const int* in_sizes, int n_in,
                              void* d_out, int out_size)
{
    const float* imgs   = (const float*)d_in[0];   // [4,256,256]
    const float* angles = (const float*)d_in[1];   // [180]
    const float* rays   = (const float*)d_in[2];   // [256,4]
    float* out          = (float*)d_out;           // [4,180,256]

    const int prep_threads = (NOUT > NPIX ? NOUT : NPIX);
    prep_kernel<<<(prep_threads + 255) / 256, 256>>>(imgs, out);

    dim3 grid(NA, 8, 2);
    radon_kernel<<<grid, 128>>>(angles, rays, out);
}